// round 1
// baseline (speedup 1.0000x reference)
#include <cuda_runtime.h>
#include <math.h>

#define NV 200000
#define NC 100000
#define NE 1200000
#define VFEAT 7
#define CFEAT 5
#define HDIM 64
#define NROUNDS 2

// ---------------- device scratch (static, allocation-free) ----------------
__device__ float g_hvar[NV * HDIM];
__device__ float g_hcon[NC * HDIM];
__device__ float g_t[NV * HDIM];          // reused: enc hidden (NV), aggC_raw (NC), t_con (NC)
__device__ int   g_deg_var[NV];
__device__ int   g_deg_con[NC];
__device__ int   g_cnt_var[NV];
__device__ int   g_cnt_con[NC];
__device__ int   g_row_var[NV + 1];
__device__ int   g_row_con[NC + 1];
__device__ int   g_adj_var[NE];            // per-var edge list: con ids
__device__ int   g_adj_con[NE];            // per-con edge list: var ids

// ---------------- zero counters ----------------
__global__ void k_zero() {
    int i = blockIdx.x * blockDim.x + threadIdx.x;
    if (i < NV) { g_deg_var[i] = 0; g_cnt_var[i] = 0; }
    if (i < NC) { g_deg_con[i] = 0; g_cnt_con[i] = 0; }
}

// ---------------- histogram ----------------
__global__ void k_hist(const int* __restrict__ ev, const int* __restrict__ ec) {
    int e = blockIdx.x * blockDim.x + threadIdx.x;
    if (e < NE) {
        atomicAdd(&g_deg_var[ev[e]], 1);
        atomicAdd(&g_deg_con[ec[e]], 1);
    }
}

// ---------------- single-block exclusive scan, 8 items/thread/tile ----------------
__global__ void k_scan(const int* __restrict__ deg, int* __restrict__ row, int n) {
    __shared__ int wsum[32];
    __shared__ int carry;
    __shared__ int btot;
    if (threadIdx.x == 0) carry = 0;
    __syncthreads();
    for (int base = 0; base < n; base += 8192) {
        int idx0 = base + threadIdx.x * 8;
        int pre[8];
        int local = 0;
        #pragma unroll
        for (int i = 0; i < 8; i++) {
            int id = idx0 + i;
            int x = (id < n) ? deg[id] : 0;
            pre[i] = local;
            local += x;
        }
        int lane = threadIdx.x & 31, w = threadIdx.x >> 5;
        int inc = local;
        #pragma unroll
        for (int o = 1; o < 32; o <<= 1) {
            int y = __shfl_up_sync(0xffffffffu, inc, o);
            if (lane >= o) inc += y;
        }
        if (lane == 31) wsum[w] = inc;
        __syncthreads();
        if (w == 0) {
            int s = wsum[lane];
            int si = s;
            #pragma unroll
            for (int o = 1; o < 32; o <<= 1) {
                int y = __shfl_up_sync(0xffffffffu, si, o);
                if (lane >= o) si += y;
            }
            wsum[lane] = si - s;
            if (lane == 31) btot = si;
        }
        __syncthreads();
        int texcl = carry + wsum[w] + (inc - local);
        #pragma unroll
        for (int i = 0; i < 8; i++) {
            int id = idx0 + i;
            if (id < n) row[id] = texcl + pre[i];
        }
        __syncthreads();
        if (threadIdx.x == 0) carry += btot;
        __syncthreads();
    }
    if (threadIdx.x == 0) row[n] = carry;
}

// ---------------- CSR fill ----------------
__global__ void k_fill(const int* __restrict__ ev, const int* __restrict__ ec) {
    int e = blockIdx.x * blockDim.x + threadIdx.x;
    if (e < NE) {
        int v = ev[e], c = ec[e];
        int pc = g_row_con[c] + atomicAdd(&g_cnt_con[c], 1);
        g_adj_con[pc] = v;
        int pv = g_row_var[v] + atomicAdd(&g_cnt_var[v], 1);
        g_adj_var[pv] = c;
    }
}

// ---------------- encoder layer 1: out = tanh(x @ W1^T + b1), F small ----------------
template <int F>
__global__ void k_enc1(const float* __restrict__ x, const float* __restrict__ W1,
                       const float* __restrict__ b1, float* __restrict__ out, int n) {
    __shared__ float Ws[64 * F];
    __shared__ float bs[64];
    int tid = threadIdx.x;
    for (int i = tid; i < 64 * F; i += 256) Ws[i] = W1[i];
    if (tid < 64) bs[tid] = b1[tid];
    __syncthreads();
    int j = tid & 63, g = tid >> 6;
    int node = blockIdx.x * 4 + g;
    if (node >= n) return;
    float acc = bs[j];
    #pragma unroll
    for (int k = 0; k < F; k++) acc += x[node * F + k] * Ws[j * F + k];
    out[node * 64 + j] = tanhf(acc);
}

// ---------------- 64x64 GEMM with fused epilogue ----------------
// out[r][j] = act( residual[r][j] + sum_k in[r][k]*W[j][k] + bias[j]*(deg?deg[r]:1) )
__global__ __launch_bounds__(256) void k_gemm64(
    const float* __restrict__ in, const float* __restrict__ W,
    const float* __restrict__ bias, const int* __restrict__ deg,
    const float* residual, float* out, int n, int act) {
    __shared__ float Wt[64][68];   // Wt[k][j]
    __shared__ float Xt[64][68];   // Xt[k][r_local]
    int tid = threadIdx.x;
    int row0 = blockIdx.x * 64;
    #pragma unroll
    for (int i = tid; i < 4096; i += 256) {
        int j = i >> 6, k = i & 63;
        Wt[k][j] = W[i];
    }
    #pragma unroll
    for (int i = tid; i < 4096; i += 256) {
        int r = i >> 6, k = i & 63;
        int row = row0 + r;
        Xt[k][r] = (row < n) ? in[row * 64 + k] : 0.f;
    }
    __syncthreads();
    int j0 = (tid & 15) * 4;
    int n0 = (tid >> 4) * 4;
    float acc[4][4];
    #pragma unroll
    for (int a = 0; a < 4; a++)
        #pragma unroll
        for (int b = 0; b < 4; b++) acc[a][b] = 0.f;
    #pragma unroll 16
    for (int k = 0; k < 64; k++) {
        float4 wv = *(const float4*)&Wt[k][j0];
        float4 xv = *(const float4*)&Xt[k][n0];
        acc[0][0] += xv.x * wv.x; acc[0][1] += xv.x * wv.y; acc[0][2] += xv.x * wv.z; acc[0][3] += xv.x * wv.w;
        acc[1][0] += xv.y * wv.x; acc[1][1] += xv.y * wv.y; acc[1][2] += xv.y * wv.z; acc[1][3] += xv.y * wv.w;
        acc[2][0] += xv.z * wv.x; acc[2][1] += xv.z * wv.y; acc[2][2] += xv.z * wv.z; acc[2][3] += xv.z * wv.w;
        acc[3][0] += xv.w * wv.x; acc[3][1] += xv.w * wv.y; acc[3][2] += xv.w * wv.z; acc[3][3] += xv.w * wv.w;
    }
    float4 bv = make_float4(0.f, 0.f, 0.f, 0.f);
    if (bias) bv = *(const float4*)&bias[j0];
    #pragma unroll
    for (int ni = 0; ni < 4; ni++) {
        int row = row0 + n0 + ni;
        if (row >= n) break;
        float s = deg ? (float)deg[row] : 1.f;
        float4 v;
        v.x = acc[ni][0] + bv.x * s;
        v.y = acc[ni][1] + bv.y * s;
        v.z = acc[ni][2] + bv.z * s;
        v.w = acc[ni][3] + bv.w * s;
        if (residual) {
            float4 rr = *(const float4*)&residual[row * 64 + j0];
            v.x += rr.x; v.y += rr.y; v.z += rr.z; v.w += rr.w;
        }
        if (act) { v.x = tanhf(v.x); v.y = tanhf(v.y); v.z = tanhf(v.z); v.w = tanhf(v.w); }
        *(float4*)&out[row * 64 + j0] = v;
    }
}

// ---------------- gather aggregation: out[d] = sum over adj of src[adj] ----------------
__global__ __launch_bounds__(256) void k_agg(
    const float* __restrict__ src, const int* __restrict__ rowp,
    const int* __restrict__ adj, float* __restrict__ out, int n) {
    int w = (blockIdx.x * 256 + threadIdx.x) >> 5;
    int lane = threadIdx.x & 31;
    if (w >= n) return;
    int b = rowp[w], e = rowp[w + 1];
    float ax = 0.f, ay = 0.f;
    int i = b;
    for (; i + 4 <= e; i += 4) {
        int v0 = adj[i], v1 = adj[i + 1], v2 = adj[i + 2], v3 = adj[i + 3];
        float2 a0 = *(const float2*)&src[v0 * 64 + lane * 2];
        float2 a1 = *(const float2*)&src[v1 * 64 + lane * 2];
        float2 a2 = *(const float2*)&src[v2 * 64 + lane * 2];
        float2 a3 = *(const float2*)&src[v3 * 64 + lane * 2];
        ax += a0.x + a1.x + a2.x + a3.x;
        ay += a0.y + a1.y + a2.y + a3.y;
    }
    for (; i < e; i++) {
        int v = adj[i];
        float2 a = *(const float2*)&src[v * 64 + lane * 2];
        ax += a.x; ay += a.y;
    }
    float2 r; r.x = ax; r.y = ay;
    *(float2*)&out[w * 64 + lane * 2] = r;
}

// ---------------- gather aggregation + fused update: h = tanh(h + agg + deg*b) ----------------
__global__ __launch_bounds__(256) void k_agg_update(
    const float* __restrict__ src, const int* __restrict__ rowp,
    const int* __restrict__ adj, float* h, const float* __restrict__ bias, int n) {
    int w = (blockIdx.x * 256 + threadIdx.x) >> 5;
    int lane = threadIdx.x & 31;
    if (w >= n) return;
    int b = rowp[w], e = rowp[w + 1];
    float ax = 0.f, ay = 0.f;
    int i = b;
    for (; i + 4 <= e; i += 4) {
        int v0 = adj[i], v1 = adj[i + 1], v2 = adj[i + 2], v3 = adj[i + 3];
        float2 a0 = *(const float2*)&src[v0 * 64 + lane * 2];
        float2 a1 = *(const float2*)&src[v1 * 64 + lane * 2];
        float2 a2 = *(const float2*)&src[v2 * 64 + lane * 2];
        float2 a3 = *(const float2*)&src[v3 * 64 + lane * 2];
        ax += a0.x + a1.x + a2.x + a3.x;
        ay += a0.y + a1.y + a2.y + a3.y;
    }
    for (; i < e; i++) {
        int v = adj[i];
        float2 a = *(const float2*)&src[v * 64 + lane * 2];
        ax += a.x; ay += a.y;
    }
    float d = (float)(e - b);
    float2 bb = *(const float2*)&bias[lane * 2];
    float2 hv = *(const float2*)&h[w * 64 + lane * 2];
    hv.x = tanhf(hv.x + ax + d * bb.x);
    hv.y = tanhf(hv.y + ay + d * bb.y);
    *(float2*)&h[w * 64 + lane * 2] = hv;
}

// ---------------- readout: out[v] = dot(h_var[v], Wro) + bro ----------------
__global__ __launch_bounds__(256) void k_readout(
    const float* __restrict__ hv, const float* __restrict__ Wro,
    const float* __restrict__ bro, float* __restrict__ out, int n) {
    int w = (blockIdx.x * 256 + threadIdx.x) >> 5;
    int lane = threadIdx.x & 31;
    if (w >= n) return;
    float2 a = *(const float2*)&hv[w * 64 + lane * 2];
    float2 ww = *(const float2*)&Wro[lane * 2];
    float s = a.x * ww.x + a.y * ww.y;
    #pragma unroll
    for (int o = 16; o; o >>= 1) s += __shfl_xor_sync(0xffffffffu, s, o);
    if (lane == 0) out[w] = s + bro[0];
}

// ---------------- launch ----------------
extern "C" void kernel_launch(void* const* d_in, const int* in_sizes, int n_in,
                              void* d_out, int out_size) {
    const float* var_features = (const float*)d_in[0];
    const float* con_features = (const float*)d_in[1];
    const int*   edge_var     = (const int*)d_in[2];
    const int*   edge_con     = (const int*)d_in[3];
    const float* W_ve1 = (const float*)d_in[4];
    const float* b_ve1 = (const float*)d_in[5];
    const float* W_ve2 = (const float*)d_in[6];
    const float* b_ve2 = (const float*)d_in[7];
    const float* W_ce1 = (const float*)d_in[8];
    const float* b_ce1 = (const float*)d_in[9];
    const float* W_ce2 = (const float*)d_in[10];
    const float* b_ce2 = (const float*)d_in[11];
    const float* W_v2c = (const float*)d_in[12];
    const float* b_v2c = (const float*)d_in[13];
    const float* W_c2v = (const float*)d_in[14];
    const float* b_c2v = (const float*)d_in[15];
    const float* W_ro  = (const float*)d_in[16];
    const float* b_ro  = (const float*)d_in[17];
    float* scores = (float*)d_out;

    // device symbol pointers
    float *hvar, *hcon, *tbuf;
    int *row_var, *row_con, *adj_var, *adj_con, *deg_var, *deg_con;
    cudaGetSymbolAddress((void**)&hvar, g_hvar);
    cudaGetSymbolAddress((void**)&hcon, g_hcon);
    cudaGetSymbolAddress((void**)&tbuf, g_t);
    cudaGetSymbolAddress((void**)&row_var, g_row_var);
    cudaGetSymbolAddress((void**)&row_con, g_row_con);
    cudaGetSymbolAddress((void**)&adj_var, g_adj_var);
    cudaGetSymbolAddress((void**)&adj_con, g_adj_con);
    cudaGetSymbolAddress((void**)&deg_var, g_deg_var);
    cudaGetSymbolAddress((void**)&deg_con, g_deg_con);

    // ---- CSR build ----
    k_zero<<<(NV + 255) / 256, 256>>>();
    k_hist<<<(NE + 255) / 256, 256>>>(edge_var, edge_con);
    k_scan<<<1, 1024>>>(deg_con, row_con, NC);
    k_scan<<<1, 1024>>>(deg_var, row_var, NV);
    k_fill<<<(NE + 255) / 256, 256>>>(edge_var, edge_con);

    // ---- encoders ----
    k_enc1<VFEAT><<<(NV + 3) / 4, 256>>>(var_features, W_ve1, b_ve1, tbuf, NV);
    k_gemm64<<<(NV + 63) / 64, 256>>>(tbuf, W_ve2, b_ve2, nullptr, nullptr, hvar, NV, 0);
    k_enc1<CFEAT><<<(NC + 3) / 4, 256>>>(con_features, W_ce1, b_ce1, tbuf, NC);
    k_gemm64<<<(NC + 63) / 64, 256>>>(tbuf, W_ce2, b_ce2, nullptr, nullptr, hcon, NC, 0);

    // ---- message passing rounds ----
    for (int r = 0; r < NROUNDS; r++) {
        // var -> con: aggregate raw h_var per con, then transform + residual + deg*bias + tanh
        k_agg<<<(NC * 32 + 255) / 256, 256>>>(hvar, row_con, adj_con, tbuf, NC);
        k_gemm64<<<(NC + 63) / 64, 256>>>(tbuf, W_v2c + r * 4096, b_v2c + r * 64,
                                          deg_con, hcon, hcon, NC, 1);
        // con -> var: transform h_con first (source side is smaller), then aggregate + update
        k_gemm64<<<(NC + 63) / 64, 256>>>(hcon, W_c2v + r * 4096, nullptr,
                                          nullptr, nullptr, tbuf, NC, 0);
        k_agg_update<<<(NV * 32 + 255) / 256, 256>>>(tbuf, row_var, adj_var, hvar,
                                                     b_c2v + r * 64, NV);
    }

    // ---- readout ----
    k_readout<<<(NV * 32 + 255) / 256, 256>>>(hvar, W_ro, b_ro, scores, NV);
}

// round 2
// speedup vs baseline: 1.5887x; 1.5887x over previous
#include <cuda_runtime.h>
#include <math.h>

#define NV 200000
#define NC 100000
#define NE 1200000
#define VFEAT 7
#define CFEAT 5
#define HDIM 64
#define NROUNDS 2
#define SCAN_TILE 2048

// ---------------- device scratch (static, allocation-free) ----------------
__device__ float g_hvar[NV * HDIM];
__device__ float g_hcon[NC * HDIM];
__device__ float g_t[NV * HDIM];
__device__ int   g_deg_var[NV];
__device__ int   g_deg_con[NC];
__device__ int   g_cnt_var[NV];
__device__ int   g_cnt_con[NC];
__device__ int   g_row_var[NV + 1];
__device__ int   g_row_con[NC + 1];
__device__ int   g_adj_var[NE];
__device__ int   g_adj_con[NE];
__device__ int   g_bsum_var[128];   // ceil(NV/2048)=98
__device__ int   g_bsum_con[64];    // ceil(NC/2048)=49

// ---------------- zero counters ----------------
__global__ void k_zero() {
    int i = blockIdx.x * blockDim.x + threadIdx.x;
    if (i < NV) { g_deg_var[i] = 0; g_cnt_var[i] = 0; }
    if (i < NC) { g_deg_con[i] = 0; g_cnt_con[i] = 0; }
}

// ---------------- histogram ----------------
__global__ void k_hist(const int* __restrict__ ev, const int* __restrict__ ec) {
    int e = blockIdx.x * blockDim.x + threadIdx.x;
    if (e < NE) {
        atomicAdd(&g_deg_var[ev[e]], 1);
        atomicAdd(&g_deg_con[ec[e]], 1);
    }
}

// ---------------- scan phase A: per-block sums ----------------
__global__ void k_scan_a(const int* __restrict__ deg, int n, int* __restrict__ bsum) {
    __shared__ int ws[8];
    int idx0 = blockIdx.x * SCAN_TILE + threadIdx.x * 8;
    int local = 0;
    #pragma unroll
    for (int i = 0; i < 8; i++) {
        int id = idx0 + i;
        if (id < n) local += deg[id];
    }
    int lane = threadIdx.x & 31, w = threadIdx.x >> 5;
    #pragma unroll
    for (int o = 16; o; o >>= 1) local += __shfl_xor_sync(0xffffffffu, local, o);
    if (lane == 0) ws[w] = local;
    __syncthreads();
    if (threadIdx.x == 0) {
        int s = 0;
        #pragma unroll
        for (int i = 0; i < 8; i++) s += ws[i];
        bsum[blockIdx.x] = s;
    }
}

// ---------------- scan phase B: exclusive scan of block sums (nb <= 128) ----------------
__global__ void k_scan_b(int* bsum, int nb) {
    __shared__ int ws[4];
    int tid = threadIdx.x;
    int v = (tid < nb) ? bsum[tid] : 0;
    int lane = tid & 31, w = tid >> 5;
    int inc = v;
    #pragma unroll
    for (int o = 1; o < 32; o <<= 1) {
        int y = __shfl_up_sync(0xffffffffu, inc, o);
        if (lane >= o) inc += y;
    }
    if (lane == 31) ws[w] = inc;
    __syncthreads();
    int add = 0;
    for (int i = 0; i < w; i++) add += ws[i];
    if (tid < nb) bsum[tid] = inc - v + add;
}

// ---------------- scan phase C: local scan + block offset ----------------
__global__ void k_scan_c(const int* __restrict__ deg, int* __restrict__ row,
                         const int* __restrict__ bsum, int n, int total) {
    __shared__ int wsum[8];
    int idx0 = blockIdx.x * SCAN_TILE + threadIdx.x * 8;
    int pre[8];
    int local = 0;
    #pragma unroll
    for (int i = 0; i < 8; i++) {
        int id = idx0 + i;
        int x = (id < n) ? deg[id] : 0;
        pre[i] = local;
        local += x;
    }
    int lane = threadIdx.x & 31, w = threadIdx.x >> 5;
    int inc = local;
    #pragma unroll
    for (int o = 1; o < 32; o <<= 1) {
        int y = __shfl_up_sync(0xffffffffu, inc, o);
        if (lane >= o) inc += y;
    }
    if (lane == 31) wsum[w] = inc;
    __syncthreads();
    int add = 0;
    for (int i = 0; i < w; i++) add += wsum[i];
    int texcl = bsum[blockIdx.x] + add + (inc - local);
    #pragma unroll
    for (int i = 0; i < 8; i++) {
        int id = idx0 + i;
        if (id < n) row[id] = texcl + pre[i];
    }
    if (blockIdx.x == 0 && threadIdx.x == 0) row[n] = total;
}

// ---------------- CSR fill ----------------
__global__ void k_fill(const int* __restrict__ ev, const int* __restrict__ ec) {
    int e = blockIdx.x * blockDim.x + threadIdx.x;
    if (e < NE) {
        int v = ev[e], c = ec[e];
        int pc = g_row_con[c] + atomicAdd(&g_cnt_con[c], 1);
        g_adj_con[pc] = v;
        int pv = g_row_var[v] + atomicAdd(&g_cnt_var[v], 1);
        g_adj_var[pv] = c;
    }
}

// ---------------- fused encoder: out = tanh(x@W1^T+b1) @ W2^T + b2 ----------------
template <int F>
__global__ __launch_bounds__(256) void k_enc(
    const float* __restrict__ x, const float* __restrict__ W1,
    const float* __restrict__ b1, const float* __restrict__ W2,
    const float* __restrict__ b2, float* __restrict__ out, int n) {
    __shared__ float W1s[64 * F];
    __shared__ float b1s[64];
    __shared__ float Xs[64][8];
    __shared__ float Wt[64][68];   // W2 transposed: Wt[k][j]
    __shared__ float Xt[64][68];   // hidden transposed: Xt[k][r]
    int tid = threadIdx.x;
    int row0 = blockIdx.x * 64;
    for (int i = tid; i < 64 * F; i += 256) W1s[i] = W1[i];
    if (tid < 64) b1s[tid] = b1[tid];
    #pragma unroll
    for (int i = tid; i < 4096; i += 256) {
        int j = i >> 6, k = i & 63;
        Wt[k][j] = W2[i];
    }
    for (int i = tid; i < 64 * F; i += 256) {
        int r = i / F, f = i % F;
        int row = row0 + r;
        Xs[r][f] = (row < n) ? x[row * F + f] : 0.f;
    }
    __syncthreads();
    // hidden layer, written transposed
    {
        int r = tid & 63;
        int k0 = tid >> 6;
        #pragma unroll
        for (int kk = 0; kk < 16; kk++) {
            int k = k0 + kk * 4;
            float acc = b1s[k];
            #pragma unroll
            for (int f = 0; f < F; f++) acc += Xs[r][f] * W1s[k * F + f];
            Xt[k][r] = tanhf(acc);
        }
    }
    __syncthreads();
    // 64x64 gemm
    int j0 = (tid & 15) * 4;
    int n0 = (tid >> 4) * 4;
    float acc[4][4];
    #pragma unroll
    for (int a = 0; a < 4; a++)
        #pragma unroll
        for (int b = 0; b < 4; b++) acc[a][b] = 0.f;
    #pragma unroll 16
    for (int k = 0; k < 64; k++) {
        float4 wv = *(const float4*)&Wt[k][j0];
        float4 xv = *(const float4*)&Xt[k][n0];
        acc[0][0] += xv.x * wv.x; acc[0][1] += xv.x * wv.y; acc[0][2] += xv.x * wv.z; acc[0][3] += xv.x * wv.w;
        acc[1][0] += xv.y * wv.x; acc[1][1] += xv.y * wv.y; acc[1][2] += xv.y * wv.z; acc[1][3] += xv.y * wv.w;
        acc[2][0] += xv.z * wv.x; acc[2][1] += xv.z * wv.y; acc[2][2] += xv.z * wv.z; acc[2][3] += xv.z * wv.w;
        acc[3][0] += xv.w * wv.x; acc[3][1] += xv.w * wv.y; acc[3][2] += xv.w * wv.z; acc[3][3] += xv.w * wv.w;
    }
    float4 bv = *(const float4*)&b2[j0];
    #pragma unroll
    for (int ni = 0; ni < 4; ni++) {
        int row = row0 + n0 + ni;
        if (row >= n) break;
        float4 v;
        v.x = acc[ni][0] + bv.x;
        v.y = acc[ni][1] + bv.y;
        v.z = acc[ni][2] + bv.z;
        v.w = acc[ni][3] + bv.w;
        *(float4*)&out[row * 64 + j0] = v;
    }
}

// ---------------- 64x64 GEMM with fused epilogue ----------------
__global__ __launch_bounds__(256) void k_gemm64(
    const float* __restrict__ in, const float* __restrict__ W,
    const float* __restrict__ bias, const int* __restrict__ deg,
    const float* residual, float* out, int n, int act) {
    __shared__ float Wt[64][68];
    __shared__ float Xt[64][68];
    int tid = threadIdx.x;
    int row0 = blockIdx.x * 64;
    #pragma unroll
    for (int i = tid; i < 4096; i += 256) {
        int j = i >> 6, k = i & 63;
        Wt[k][j] = W[i];
    }
    #pragma unroll
    for (int i = tid; i < 4096; i += 256) {
        int r = i >> 6, k = i & 63;
        int row = row0 + r;
        Xt[k][r] = (row < n) ? in[row * 64 + k] : 0.f;
    }
    __syncthreads();
    int j0 = (tid & 15) * 4;
    int n0 = (tid >> 4) * 4;
    float acc[4][4];
    #pragma unroll
    for (int a = 0; a < 4; a++)
        #pragma unroll
        for (int b = 0; b < 4; b++) acc[a][b] = 0.f;
    #pragma unroll 16
    for (int k = 0; k < 64; k++) {
        float4 wv = *(const float4*)&Wt[k][j0];
        float4 xv = *(const float4*)&Xt[k][n0];
        acc[0][0] += xv.x * wv.x; acc[0][1] += xv.x * wv.y; acc[0][2] += xv.x * wv.z; acc[0][3] += xv.x * wv.w;
        acc[1][0] += xv.y * wv.x; acc[1][1] += xv.y * wv.y; acc[1][2] += xv.y * wv.z; acc[1][3] += xv.y * wv.w;
        acc[2][0] += xv.z * wv.x; acc[2][1] += xv.z * wv.y; acc[2][2] += xv.z * wv.z; acc[2][3] += xv.z * wv.w;
        acc[3][0] += xv.w * wv.x; acc[3][1] += xv.w * wv.y; acc[3][2] += xv.w * wv.z; acc[3][3] += xv.w * wv.w;
    }
    float4 bv = make_float4(0.f, 0.f, 0.f, 0.f);
    if (bias) bv = *(const float4*)&bias[j0];
    #pragma unroll
    for (int ni = 0; ni < 4; ni++) {
        int row = row0 + n0 + ni;
        if (row >= n) break;
        float s = deg ? (float)deg[row] : 1.f;
        float4 v;
        v.x = acc[ni][0] + bv.x * s;
        v.y = acc[ni][1] + bv.y * s;
        v.z = acc[ni][2] + bv.z * s;
        v.w = acc[ni][3] + bv.w * s;
        if (residual) {
            float4 rr = *(const float4*)&residual[row * 64 + j0];
            v.x += rr.x; v.y += rr.y; v.z += rr.z; v.w += rr.w;
        }
        if (act) { v.x = tanhf(v.x); v.y = tanhf(v.y); v.z = tanhf(v.z); v.w = tanhf(v.w); }
        *(float4*)&out[row * 64 + j0] = v;
    }
}

// ---------------- gather aggregation: out[d] = sum over adj of src[adj] ----------------
__global__ __launch_bounds__(256) void k_agg(
    const float* __restrict__ src, const int* __restrict__ rowp,
    const int* __restrict__ adj, float* __restrict__ out, int n) {
    int w = (blockIdx.x * 256 + threadIdx.x) >> 5;
    int lane = threadIdx.x & 31;
    if (w >= n) return;
    int b = rowp[w], e = rowp[w + 1];
    float ax = 0.f, ay = 0.f;
    int i = b;
    for (; i + 4 <= e; i += 4) {
        int v0 = adj[i], v1 = adj[i + 1], v2 = adj[i + 2], v3 = adj[i + 3];
        float2 a0 = *(const float2*)&src[v0 * 64 + lane * 2];
        float2 a1 = *(const float2*)&src[v1 * 64 + lane * 2];
        float2 a2 = *(const float2*)&src[v2 * 64 + lane * 2];
        float2 a3 = *(const float2*)&src[v3 * 64 + lane * 2];
        ax += a0.x + a1.x + a2.x + a3.x;
        ay += a0.y + a1.y + a2.y + a3.y;
    }
    for (; i < e; i++) {
        int v = adj[i];
        float2 a = *(const float2*)&src[v * 64 + lane * 2];
        ax += a.x; ay += a.y;
    }
    float2 r; r.x = ax; r.y = ay;
    *(float2*)&out[w * 64 + lane * 2] = r;
}

// ---------------- gather aggregation + fused update: h = tanh(h + agg + deg*b) ----------------
__global__ __launch_bounds__(256) void k_agg_update(
    const float* __restrict__ src, const int* __restrict__ rowp,
    const int* __restrict__ adj, float* h, const float* __restrict__ bias, int n) {
    int w = (blockIdx.x * 256 + threadIdx.x) >> 5;
    int lane = threadIdx.x & 31;
    if (w >= n) return;
    int b = rowp[w], e = rowp[w + 1];
    float ax = 0.f, ay = 0.f;
    int i = b;
    for (; i + 4 <= e; i += 4) {
        int v0 = adj[i], v1 = adj[i + 1], v2 = adj[i + 2], v3 = adj[i + 3];
        float2 a0 = *(const float2*)&src[v0 * 64 + lane * 2];
        float2 a1 = *(const float2*)&src[v1 * 64 + lane * 2];
        float2 a2 = *(const float2*)&src[v2 * 64 + lane * 2];
        float2 a3 = *(const float2*)&src[v3 * 64 + lane * 2];
        ax += a0.x + a1.x + a2.x + a3.x;
        ay += a0.y + a1.y + a2.y + a3.y;
    }
    for (; i < e; i++) {
        int v = adj[i];
        float2 a = *(const float2*)&src[v * 64 + lane * 2];
        ax += a.x; ay += a.y;
    }
    float d = (float)(e - b);
    float2 bb = *(const float2*)&bias[lane * 2];
    float2 hv = *(const float2*)&h[w * 64 + lane * 2];
    hv.x = tanhf(hv.x + ax + d * bb.x);
    hv.y = tanhf(hv.y + ay + d * bb.y);
    *(float2*)&h[w * 64 + lane * 2] = hv;
}

// ---------------- final round: agg + update + readout fused ----------------
__global__ __launch_bounds__(256) void k_agg_update_ro(
    const float* __restrict__ src, const int* __restrict__ rowp,
    const int* __restrict__ adj, const float* __restrict__ h,
    const float* __restrict__ bias, const float* __restrict__ Wro,
    const float* __restrict__ bro, float* __restrict__ scores, int n) {
    int w = (blockIdx.x * 256 + threadIdx.x) >> 5;
    int lane = threadIdx.x & 31;
    if (w >= n) return;
    int b = rowp[w], e = rowp[w + 1];
    float ax = 0.f, ay = 0.f;
    int i = b;
    for (; i + 4 <= e; i += 4) {
        int v0 = adj[i], v1 = adj[i + 1], v2 = adj[i + 2], v3 = adj[i + 3];
        float2 a0 = *(const float2*)&src[v0 * 64 + lane * 2];
        float2 a1 = *(const float2*)&src[v1 * 64 + lane * 2];
        float2 a2 = *(const float2*)&src[v2 * 64 + lane * 2];
        float2 a3 = *(const float2*)&src[v3 * 64 + lane * 2];
        ax += a0.x + a1.x + a2.x + a3.x;
        ay += a0.y + a1.y + a2.y + a3.y;
    }
    for (; i < e; i++) {
        int v = adj[i];
        float2 a = *(const float2*)&src[v * 64 + lane * 2];
        ax += a.x; ay += a.y;
    }
    float d = (float)(e - b);
    float2 bb = *(const float2*)&bias[lane * 2];
    float2 hv = *(const float2*)&h[w * 64 + lane * 2];
    float hx = tanhf(hv.x + ax + d * bb.x);
    float hy = tanhf(hv.y + ay + d * bb.y);
    float2 ww = *(const float2*)&Wro[lane * 2];
    float s = hx * ww.x + hy * ww.y;
    #pragma unroll
    for (int o = 16; o; o >>= 1) s += __shfl_xor_sync(0xffffffffu, s, o);
    if (lane == 0) scores[w] = s + bro[0];
}

// ---------------- launch ----------------
extern "C" void kernel_launch(void* const* d_in, const int* in_sizes, int n_in,
                              void* d_out, int out_size) {
    const float* var_features = (const float*)d_in[0];
    const float* con_features = (const float*)d_in[1];
    const int*   edge_var     = (const int*)d_in[2];
    const int*   edge_con     = (const int*)d_in[3];
    const float* W_ve1 = (const float*)d_in[4];
    const float* b_ve1 = (const float*)d_in[5];
    const float* W_ve2 = (const float*)d_in[6];
    const float* b_ve2 = (const float*)d_in[7];
    const float* W_ce1 = (const float*)d_in[8];
    const float* b_ce1 = (const float*)d_in[9];
    const float* W_ce2 = (const float*)d_in[10];
    const float* b_ce2 = (const float*)d_in[11];
    const float* W_v2c = (const float*)d_in[12];
    const float* b_v2c = (const float*)d_in[13];
    const float* W_c2v = (const float*)d_in[14];
    const float* b_c2v = (const float*)d_in[15];
    const float* W_ro  = (const float*)d_in[16];
    const float* b_ro  = (const float*)d_in[17];
    float* scores = (float*)d_out;

    float *hvar, *hcon, *tbuf;
    int *row_var, *row_con, *adj_var, *adj_con, *deg_var, *deg_con, *bsv, *bsc;
    cudaGetSymbolAddress((void**)&hvar, g_hvar);
    cudaGetSymbolAddress((void**)&hcon, g_hcon);
    cudaGetSymbolAddress((void**)&tbuf, g_t);
    cudaGetSymbolAddress((void**)&row_var, g_row_var);
    cudaGetSymbolAddress((void**)&row_con, g_row_con);
    cudaGetSymbolAddress((void**)&adj_var, g_adj_var);
    cudaGetSymbolAddress((void**)&adj_con, g_adj_con);
    cudaGetSymbolAddress((void**)&deg_var, g_deg_var);
    cudaGetSymbolAddress((void**)&deg_con, g_deg_con);
    cudaGetSymbolAddress((void**)&bsv, g_bsum_var);
    cudaGetSymbolAddress((void**)&bsc, g_bsum_con);

    const int NBV = (NV + SCAN_TILE - 1) / SCAN_TILE;   // 98
    const int NBC = (NC + SCAN_TILE - 1) / SCAN_TILE;   // 49

    // ---- CSR build ----
    k_zero<<<(NV + 255) / 256, 256>>>();
    k_hist<<<(NE + 255) / 256, 256>>>(edge_var, edge_con);
    k_scan_a<<<NBC, 256>>>(deg_con, NC, bsc);
    k_scan_b<<<1, 128>>>(bsc, NBC);
    k_scan_c<<<NBC, 256>>>(deg_con, row_con, bsc, NC, NE);
    k_scan_a<<<NBV, 256>>>(deg_var, NV, bsv);
    k_scan_b<<<1, 128>>>(bsv, NBV);
    k_scan_c<<<NBV, 256>>>(deg_var, row_var, bsv, NV, NE);
    k_fill<<<(NE + 255) / 256, 256>>>(edge_var, edge_con);

    // ---- encoders (fused 2-layer MLP) ----
    k_enc<VFEAT><<<(NV + 63) / 64, 256>>>(var_features, W_ve1, b_ve1, W_ve2, b_ve2, hvar, NV);
    k_enc<CFEAT><<<(NC + 63) / 64, 256>>>(con_features, W_ce1, b_ce1, W_ce2, b_ce2, hcon, NC);

    // ---- message passing rounds ----
    for (int r = 0; r < NROUNDS; r++) {
        // var -> con
        k_agg<<<(NC * 32 + 255) / 256, 256>>>(hvar, row_con, adj_con, tbuf, NC);
        k_gemm64<<<(NC + 63) / 64, 256>>>(tbuf, W_v2c + r * 4096, b_v2c + r * 64,
                                          deg_con, hcon, hcon, NC, 1);
        // con -> var
        k_gemm64<<<(NC + 63) / 64, 256>>>(hcon, W_c2v + r * 4096, nullptr,
                                          nullptr, nullptr, tbuf, NC, 0);
        if (r < NROUNDS - 1) {
            k_agg_update<<<(NV * 32 + 255) / 256, 256>>>(tbuf, row_var, adj_var, hvar,
                                                         b_c2v + r * 64, NV);
        } else {
            k_agg_update_ro<<<(NV * 32 + 255) / 256, 256>>>(tbuf, row_var, adj_var, hvar,
                                                            b_c2v + r * 64, W_ro, b_ro,
                                                            scores, NV);
        }
    }
}

// round 3
// speedup vs baseline: 1.6148x; 1.0164x over previous
#include <cuda_runtime.h>
#include <math.h>
#include <string.h>

#define NV 200000
#define NC 100000
#define NE 1200000
#define VFEAT 7
#define CFEAT 5
#define HDIM 64
#define NROUNDS 2
#define SCAN_TILE 2048

typedef unsigned long long ull;

// ---------------- packed f32x2 helpers (Blackwell) ----------------
__device__ __forceinline__ ull bcast2(float x) {
    ull r;
    unsigned u = __float_as_uint(x);
    asm("mov.b64 %0, {%1, %1};" : "=l"(r) : "r"(u));
    return r;
}
__device__ __forceinline__ void ffma2(ull& d, ull a, ull b) {
    asm("fma.rn.f32x2 %0, %1, %2, %0;" : "+l"(d) : "l"(a), "l"(b));
}
__device__ __forceinline__ float2 unpack2(ull v) {
    float2 f;
    memcpy(&f, &v, 8);
    return f;
}

// ---------------- device scratch (static, allocation-free) ----------------
__device__ float g_hvar[NV * HDIM];
__device__ float g_hcon[NC * HDIM];
__device__ float g_t[NV * HDIM];
__device__ int   g_deg_var[NV];
__device__ int   g_deg_con[NC];
__device__ int   g_cnt_var[NV];
__device__ int   g_cnt_con[NC];
__device__ int   g_row_var[NV + 1];
__device__ int   g_row_con[NC + 1];
__device__ int   g_adj_var[NE];
__device__ int   g_adj_con[NE];
__device__ int   g_bsum_var[128];
__device__ int   g_bsum_con[64];

// ---------------- zero counters ----------------
__global__ void k_zero() {
    int i = blockIdx.x * blockDim.x + threadIdx.x;
    if (i < NV) { g_deg_var[i] = 0; g_cnt_var[i] = 0; }
    if (i < NC) { g_deg_con[i] = 0; g_cnt_con[i] = 0; }
}

// ---------------- histogram ----------------
__global__ void k_hist(const int* __restrict__ ev, const int* __restrict__ ec) {
    int e = blockIdx.x * blockDim.x + threadIdx.x;
    if (e < NE) {
        atomicAdd(&g_deg_var[ev[e]], 1);
        atomicAdd(&g_deg_con[ec[e]], 1);
    }
}

// ---------------- scan phase A: per-block sums ----------------
__global__ void k_scan_a(const int* __restrict__ deg, int n, int* __restrict__ bsum) {
    __shared__ int ws[8];
    int idx0 = blockIdx.x * SCAN_TILE + threadIdx.x * 8;
    int local = 0;
    #pragma unroll
    for (int i = 0; i < 8; i++) {
        int id = idx0 + i;
        if (id < n) local += deg[id];
    }
    int lane = threadIdx.x & 31, w = threadIdx.x >> 5;
    #pragma unroll
    for (int o = 16; o; o >>= 1) local += __shfl_xor_sync(0xffffffffu, local, o);
    if (lane == 0) ws[w] = local;
    __syncthreads();
    if (threadIdx.x == 0) {
        int s = 0;
        #pragma unroll
        for (int i = 0; i < 8; i++) s += ws[i];
        bsum[blockIdx.x] = s;
    }
}

// ---------------- scan phase B: exclusive scan of block sums (nb <= 128) ----------------
__global__ void k_scan_b(int* bsum, int nb) {
    __shared__ int ws[4];
    int tid = threadIdx.x;
    int v = (tid < nb) ? bsum[tid] : 0;
    int lane = tid & 31, w = tid >> 5;
    int inc = v;
    #pragma unroll
    for (int o = 1; o < 32; o <<= 1) {
        int y = __shfl_up_sync(0xffffffffu, inc, o);
        if (lane >= o) inc += y;
    }
    if (lane == 31) ws[w] = inc;
    __syncthreads();
    int add = 0;
    for (int i = 0; i < w; i++) add += ws[i];
    if (tid < nb) bsum[tid] = inc - v + add;
}

// ---------------- scan phase C: local scan + block offset ----------------
__global__ void k_scan_c(const int* __restrict__ deg, int* __restrict__ row,
                         const int* __restrict__ bsum, int n, int total) {
    __shared__ int wsum[8];
    int idx0 = blockIdx.x * SCAN_TILE + threadIdx.x * 8;
    int pre[8];
    int local = 0;
    #pragma unroll
    for (int i = 0; i < 8; i++) {
        int id = idx0 + i;
        int x = (id < n) ? deg[id] : 0;
        pre[i] = local;
        local += x;
    }
    int lane = threadIdx.x & 31, w = threadIdx.x >> 5;
    int inc = local;
    #pragma unroll
    for (int o = 1; o < 32; o <<= 1) {
        int y = __shfl_up_sync(0xffffffffu, inc, o);
        if (lane >= o) inc += y;
    }
    if (lane == 31) wsum[w] = inc;
    __syncthreads();
    int add = 0;
    for (int i = 0; i < w; i++) add += wsum[i];
    int texcl = bsum[blockIdx.x] + add + (inc - local);
    #pragma unroll
    for (int i = 0; i < 8; i++) {
        int id = idx0 + i;
        if (id < n) row[id] = texcl + pre[i];
    }
    if (blockIdx.x == 0 && threadIdx.x == 0) row[n] = total;
}

// ---------------- CSR fill ----------------
__global__ void k_fill(const int* __restrict__ ev, const int* __restrict__ ec) {
    int e = blockIdx.x * blockDim.x + threadIdx.x;
    if (e < NE) {
        int v = ev[e], c = ec[e];
        int pc = g_row_con[c] + atomicAdd(&g_cnt_con[c], 1);
        g_adj_con[pc] = v;
        int pv = g_row_var[v] + atomicAdd(&g_cnt_var[v], 1);
        g_adj_var[pv] = c;
    }
}

// ---------------- fused encoder: out = tanh(x@W1^T+b1) @ W2^T + b2 ----------------
template <int F>
__global__ __launch_bounds__(256) void k_enc(
    const float* __restrict__ x, const float* __restrict__ W1,
    const float* __restrict__ b1, const float* __restrict__ W2,
    const float* __restrict__ b2, float* __restrict__ out, int n) {
    __shared__ float W1s[64 * F];
    __shared__ float b1s[64];
    __shared__ float Xs[64][8];
    __shared__ float Wt[64][68];
    __shared__ float Xt[64][68];
    int tid = threadIdx.x;
    int row0 = blockIdx.x * 64;
    for (int i = tid; i < 64 * F; i += 256) W1s[i] = W1[i];
    if (tid < 64) b1s[tid] = b1[tid];
    #pragma unroll
    for (int i = tid; i < 4096; i += 256) {
        int j = i >> 6, k = i & 63;
        Wt[k][j] = W2[i];
    }
    for (int i = tid; i < 64 * F; i += 256) {
        int r = i / F, f = i % F;
        int row = row0 + r;
        Xs[r][f] = (row < n) ? x[row * F + f] : 0.f;
    }
    __syncthreads();
    {
        int r = tid & 63;
        int k0 = tid >> 6;
        #pragma unroll
        for (int kk = 0; kk < 16; kk++) {
            int k = k0 + kk * 4;
            float acc = b1s[k];
            #pragma unroll
            for (int f = 0; f < F; f++) acc += Xs[r][f] * W1s[k * F + f];
            Xt[k][r] = tanhf(acc);
        }
    }
    __syncthreads();
    int j0 = (tid & 15) * 4;
    int n0 = (tid >> 4) * 4;
    ull acc2[4][2];
    #pragma unroll
    for (int a = 0; a < 4; a++) { acc2[a][0] = 0ull; acc2[a][1] = 0ull; }
    #pragma unroll 16
    for (int k = 0; k < 64; k++) {
        ulonglong2 wv = *(const ulonglong2*)&Wt[k][j0];
        float4 xv = *(const float4*)&Xt[k][n0];
        ull x0 = bcast2(xv.x), x1 = bcast2(xv.y), x2 = bcast2(xv.z), x3 = bcast2(xv.w);
        ffma2(acc2[0][0], x0, wv.x); ffma2(acc2[0][1], x0, wv.y);
        ffma2(acc2[1][0], x1, wv.x); ffma2(acc2[1][1], x1, wv.y);
        ffma2(acc2[2][0], x2, wv.x); ffma2(acc2[2][1], x2, wv.y);
        ffma2(acc2[3][0], x3, wv.x); ffma2(acc2[3][1], x3, wv.y);
    }
    float4 bv = *(const float4*)&b2[j0];
    #pragma unroll
    for (int ni = 0; ni < 4; ni++) {
        int row = row0 + n0 + ni;
        if (row >= n) break;
        float2 lo = unpack2(acc2[ni][0]);
        float2 hi = unpack2(acc2[ni][1]);
        float4 v;
        v.x = lo.x + bv.x; v.y = lo.y + bv.y; v.z = hi.x + bv.z; v.w = hi.y + bv.w;
        *(float4*)&out[row * 64 + j0] = v;
    }
}

// ---------------- fused round GEMM pair ----------------
// h = tanh(hcon + agg@W1^T + deg*b1)  -> stored to hcon
// t = h@W2^T                          -> stored to tout
__global__ __launch_bounds__(256) void k_gemm_pair(
    const float* __restrict__ agg, const float* __restrict__ W1,
    const float* __restrict__ b1, const int* __restrict__ deg,
    float* hcon, const float* __restrict__ W2, float* __restrict__ tout, int n) {
    __shared__ float W1t[64][68];
    __shared__ float W2t[64][68];
    __shared__ float Xt[64][68];
    int tid = threadIdx.x;
    int row0 = blockIdx.x * 64;
    #pragma unroll
    for (int i = tid; i < 4096; i += 256) {
        int j = i >> 6, k = i & 63;
        W1t[k][j] = W1[i];
        W2t[k][j] = W2[i];
    }
    #pragma unroll
    for (int i = tid; i < 4096; i += 256) {
        int r = i >> 6, k = i & 63;
        int row = row0 + r;
        Xt[k][r] = (row < n) ? agg[row * 64 + k] : 0.f;
    }
    __syncthreads();
    int j0 = (tid & 15) * 4;
    int n0 = (tid >> 4) * 4;
    ull acc2[4][2];
    #pragma unroll
    for (int a = 0; a < 4; a++) { acc2[a][0] = 0ull; acc2[a][1] = 0ull; }
    #pragma unroll 16
    for (int k = 0; k < 64; k++) {
        ulonglong2 wv = *(const ulonglong2*)&W1t[k][j0];
        float4 xv = *(const float4*)&Xt[k][n0];
        ull x0 = bcast2(xv.x), x1 = bcast2(xv.y), x2 = bcast2(xv.z), x3 = bcast2(xv.w);
        ffma2(acc2[0][0], x0, wv.x); ffma2(acc2[0][1], x0, wv.y);
        ffma2(acc2[1][0], x1, wv.x); ffma2(acc2[1][1], x1, wv.y);
        ffma2(acc2[2][0], x2, wv.x); ffma2(acc2[2][1], x2, wv.y);
        ffma2(acc2[3][0], x3, wv.x); ffma2(acc2[3][1], x3, wv.y);
    }
    __syncthreads();   // all Xt reads done; safe to overwrite
    float4 bv = *(const float4*)&b1[j0];
    float hv[4][4];
    #pragma unroll
    for (int ni = 0; ni < 4; ni++) {
        int row = row0 + n0 + ni;
        float2 lo = unpack2(acc2[ni][0]);
        float2 hi = unpack2(acc2[ni][1]);
        float a0 = lo.x, a1 = lo.y, a2 = hi.x, a3 = hi.y;
        if (row < n) {
            float s = (float)deg[row];
            float4 rr = *(const float4*)&hcon[row * 64 + j0];
            a0 = tanhf(a0 + bv.x * s + rr.x);
            a1 = tanhf(a1 + bv.y * s + rr.y);
            a2 = tanhf(a2 + bv.z * s + rr.z);
            a3 = tanhf(a3 + bv.w * s + rr.w);
            float4 v; v.x = a0; v.y = a1; v.z = a2; v.w = a3;
            *(float4*)&hcon[row * 64 + j0] = v;
        } else {
            a0 = a1 = a2 = a3 = 0.f;
        }
        hv[ni][0] = a0; hv[ni][1] = a1; hv[ni][2] = a2; hv[ni][3] = a3;
    }
    // transpose h into Xt: Xt[col][row_local]
    #pragma unroll
    for (int ni = 0; ni < 4; ni++) {
        #pragma unroll
        for (int jj = 0; jj < 4; jj++) {
            Xt[j0 + jj][n0 + ni] = hv[ni][jj];
        }
    }
    __syncthreads();
    // second gemm: t = h @ W2^T
    #pragma unroll
    for (int a = 0; a < 4; a++) { acc2[a][0] = 0ull; acc2[a][1] = 0ull; }
    #pragma unroll 16
    for (int k = 0; k < 64; k++) {
        ulonglong2 wv = *(const ulonglong2*)&W2t[k][j0];
        float4 xv = *(const float4*)&Xt[k][n0];
        ull x0 = bcast2(xv.x), x1 = bcast2(xv.y), x2 = bcast2(xv.z), x3 = bcast2(xv.w);
        ffma2(acc2[0][0], x0, wv.x); ffma2(acc2[0][1], x0, wv.y);
        ffma2(acc2[1][0], x1, wv.x); ffma2(acc2[1][1], x1, wv.y);
        ffma2(acc2[2][0], x2, wv.x); ffma2(acc2[2][1], x2, wv.y);
        ffma2(acc2[3][0], x3, wv.x); ffma2(acc2[3][1], x3, wv.y);
    }
    #pragma unroll
    for (int ni = 0; ni < 4; ni++) {
        int row = row0 + n0 + ni;
        if (row >= n) break;
        float2 lo = unpack2(acc2[ni][0]);
        float2 hi = unpack2(acc2[ni][1]);
        float4 v; v.x = lo.x; v.y = lo.y; v.z = hi.x; v.w = hi.y;
        *(float4*)&tout[row * 64 + j0] = v;
    }
}

// ---------------- gather aggregation: out[d] = sum over adj of src[adj] ----------------
__global__ __launch_bounds__(256) void k_agg(
    const float* __restrict__ src, const int* __restrict__ rowp,
    const int* __restrict__ adj, float* __restrict__ out, int n) {
    int w = (blockIdx.x * 256 + threadIdx.x) >> 5;
    int lane = threadIdx.x & 31;
    if (w >= n) return;
    int b = rowp[w], e = rowp[w + 1];
    float ax = 0.f, ay = 0.f;
    int i = b;
    for (; i + 4 <= e; i += 4) {
        int v0 = adj[i], v1 = adj[i + 1], v2 = adj[i + 2], v3 = adj[i + 3];
        float2 a0 = *(const float2*)&src[v0 * 64 + lane * 2];
        float2 a1 = *(const float2*)&src[v1 * 64 + lane * 2];
        float2 a2 = *(const float2*)&src[v2 * 64 + lane * 2];
        float2 a3 = *(const float2*)&src[v3 * 64 + lane * 2];
        ax += a0.x + a1.x + a2.x + a3.x;
        ay += a0.y + a1.y + a2.y + a3.y;
    }
    for (; i < e; i++) {
        int v = adj[i];
        float2 a = *(const float2*)&src[v * 64 + lane * 2];
        ax += a.x; ay += a.y;
    }
    float2 r; r.x = ax; r.y = ay;
    *(float2*)&out[w * 64 + lane * 2] = r;
}

// ---------------- gather aggregation + fused update: h = tanh(h + agg + deg*b) ----------------
__global__ __launch_bounds__(256) void k_agg_update(
    const float* __restrict__ src, const int* __restrict__ rowp,
    const int* __restrict__ adj, float* h, const float* __restrict__ bias, int n) {
    int w = (blockIdx.x * 256 + threadIdx.x) >> 5;
    int lane = threadIdx.x & 31;
    if (w >= n) return;
    int b = rowp[w], e = rowp[w + 1];
    float ax = 0.f, ay = 0.f;
    int i = b;
    for (; i + 4 <= e; i += 4) {
        int v0 = adj[i], v1 = adj[i + 1], v2 = adj[i + 2], v3 = adj[i + 3];
        float2 a0 = *(const float2*)&src[v0 * 64 + lane * 2];
        float2 a1 = *(const float2*)&src[v1 * 64 + lane * 2];
        float2 a2 = *(const float2*)&src[v2 * 64 + lane * 2];
        float2 a3 = *(const float2*)&src[v3 * 64 + lane * 2];
        ax += a0.x + a1.x + a2.x + a3.x;
        ay += a0.y + a1.y + a2.y + a3.y;
    }
    for (; i < e; i++) {
        int v = adj[i];
        float2 a = *(const float2*)&src[v * 64 + lane * 2];
        ax += a.x; ay += a.y;
    }
    float d = (float)(e - b);
    float2 bb = *(const float2*)&bias[lane * 2];
    float2 hv = *(const float2*)&h[w * 64 + lane * 2];
    hv.x = tanhf(hv.x + ax + d * bb.x);
    hv.y = tanhf(hv.y + ay + d * bb.y);
    *(float2*)&h[w * 64 + lane * 2] = hv;
}

// ---------------- final round: agg + update + readout fused ----------------
__global__ __launch_bounds__(256) void k_agg_update_ro(
    const float* __restrict__ src, const int* __restrict__ rowp,
    const int* __restrict__ adj, const float* __restrict__ h,
    const float* __restrict__ bias, const float* __restrict__ Wro,
    const float* __restrict__ bro, float* __restrict__ scores, int n) {
    int w = (blockIdx.x * 256 + threadIdx.x) >> 5;
    int lane = threadIdx.x & 31;
    if (w >= n) return;
    int b = rowp[w], e = rowp[w + 1];
    float ax = 0.f, ay = 0.f;
    int i = b;
    for (; i + 4 <= e; i += 4) {
        int v0 = adj[i], v1 = adj[i + 1], v2 = adj[i + 2], v3 = adj[i + 3];
        float2 a0 = *(const float2*)&src[v0 * 64 + lane * 2];
        float2 a1 = *(const float2*)&src[v1 * 64 + lane * 2];
        float2 a2 = *(const float2*)&src[v2 * 64 + lane * 2];
        float2 a3 = *(const float2*)&src[v3 * 64 + lane * 2];
        ax += a0.x + a1.x + a2.x + a3.x;
        ay += a0.y + a1.y + a2.y + a3.y;
    }
    for (; i < e; i++) {
        int v = adj[i];
        float2 a = *(const float2*)&src[v * 64 + lane * 2];
        ax += a.x; ay += a.y;
    }
    float d = (float)(e - b);
    float2 bb = *(const float2*)&bias[lane * 2];
    float2 hv = *(const float2*)&h[w * 64 + lane * 2];
    float hx = tanhf(hv.x + ax + d * bb.x);
    float hy = tanhf(hv.y + ay + d * bb.y);
    float2 ww = *(const float2*)&Wro[lane * 2];
    float s = hx * ww.x + hy * ww.y;
    #pragma unroll
    for (int o = 16; o; o >>= 1) s += __shfl_xor_sync(0xffffffffu, s, o);
    if (lane == 0) scores[w] = s + bro[0];
}

// ---------------- launch ----------------
extern "C" void kernel_launch(void* const* d_in, const int* in_sizes, int n_in,
                              void* d_out, int out_size) {
    const float* var_features = (const float*)d_in[0];
    const float* con_features = (const float*)d_in[1];
    const int*   edge_var     = (const int*)d_in[2];
    const int*   edge_con     = (const int*)d_in[3];
    const float* W_ve1 = (const float*)d_in[4];
    const float* b_ve1 = (const float*)d_in[5];
    const float* W_ve2 = (const float*)d_in[6];
    const float* b_ve2 = (const float*)d_in[7];
    const float* W_ce1 = (const float*)d_in[8];
    const float* b_ce1 = (const float*)d_in[9];
    const float* W_ce2 = (const float*)d_in[10];
    const float* b_ce2 = (const float*)d_in[11];
    const float* W_v2c = (const float*)d_in[12];
    const float* b_v2c = (const float*)d_in[13];
    const float* W_c2v = (const float*)d_in[14];
    const float* b_c2v = (const float*)d_in[15];
    const float* W_ro  = (const float*)d_in[16];
    const float* b_ro  = (const float*)d_in[17];
    float* scores = (float*)d_out;

    float *hvar, *hcon, *tbuf;
    int *row_var, *row_con, *adj_var, *adj_con, *deg_var, *deg_con, *bsv, *bsc;
    cudaGetSymbolAddress((void**)&hvar, g_hvar);
    cudaGetSymbolAddress((void**)&hcon, g_hcon);
    cudaGetSymbolAddress((void**)&tbuf, g_t);
    cudaGetSymbolAddress((void**)&row_var, g_row_var);
    cudaGetSymbolAddress((void**)&row_con, g_row_con);
    cudaGetSymbolAddress((void**)&adj_var, g_adj_var);
    cudaGetSymbolAddress((void**)&adj_con, g_adj_con);
    cudaGetSymbolAddress((void**)&deg_var, g_deg_var);
    cudaGetSymbolAddress((void**)&deg_con, g_deg_con);
    cudaGetSymbolAddress((void**)&bsv, g_bsum_var);
    cudaGetSymbolAddress((void**)&bsc, g_bsum_con);

    const int NBV = (NV + SCAN_TILE - 1) / SCAN_TILE;
    const int NBC = (NC + SCAN_TILE - 1) / SCAN_TILE;

    // ---- CSR build ----
    k_zero<<<(NV + 255) / 256, 256>>>();
    k_hist<<<(NE + 255) / 256, 256>>>(edge_var, edge_con);
    k_scan_a<<<NBC, 256>>>(deg_con, NC, bsc);
    k_scan_b<<<1, 128>>>(bsc, NBC);
    k_scan_c<<<NBC, 256>>>(deg_con, row_con, bsc, NC, NE);
    k_scan_a<<<NBV, 256>>>(deg_var, NV, bsv);
    k_scan_b<<<1, 128>>>(bsv, NBV);
    k_scan_c<<<NBV, 256>>>(deg_var, row_var, bsv, NV, NE);
    k_fill<<<(NE + 255) / 256, 256>>>(edge_var, edge_con);

    // ---- encoders ----
    k_enc<VFEAT><<<(NV + 63) / 64, 256>>>(var_features, W_ve1, b_ve1, W_ve2, b_ve2, hvar, NV);
    k_enc<CFEAT><<<(NC + 63) / 64, 256>>>(con_features, W_ce1, b_ce1, W_ce2, b_ce2, hcon, NC);

    // ---- message passing rounds ----
    for (int r = 0; r < NROUNDS; r++) {
        k_agg<<<(NC * 32 + 255) / 256, 256>>>(hvar, row_con, adj_con, tbuf, NC);
        k_gemm_pair<<<(NC + 63) / 64, 256>>>(tbuf, W_v2c + r * 4096, b_v2c + r * 64,
                                             deg_con, hcon, W_c2v + r * 4096, tbuf, NC);
        if (r < NROUNDS - 1) {
            k_agg_update<<<(NV * 32 + 255) / 256, 256>>>(tbuf, row_var, adj_var, hvar,
                                                         b_c2v + r * 64, NV);
        } else {
            k_agg_update_ro<<<(NV * 32 + 255) / 256, 256>>>(tbuf, row_var, adj_var, hvar,
                                                            b_c2v + r * 64, W_ro, b_ro,
                                                            scores, NV);
        }
    }
}